// round 7
// baseline (speedup 1.0000x reference)
#include <cuda_runtime.h>
#include <cuda_fp16.h>
#include <mma.h>
#include <math.h>
#include <float.h>
#include <stdint.h>
#include <type_traits>

using namespace nvcuda;

#define NROWS 8192
#define DIN   1024
#define DD    512
#define DH    256      // D/2
#define TK    6
#define NTILE 32       // NROWS / 256 column tiles in logits GEMM
#define NCAND (NTILE * TK)   // 192 candidates per row
#define NCHUNK 64
#define ROWS_PER_CHUNK (NROWS / NCHUNK)
#define LN_EPS 1e-5f
#define SCALE_LOGITS 0.044194173824159216f  // 512^-0.5

// ------------------------- scratch (device globals; no cudaMalloc allowed) ---
__device__ float  g_h[NROWS * DD];
__device__ float  g_eh[NROWS * DD];
__device__ float  g_et[NROWS * DD];
__device__ float  g_cand_v[NROWS * NCAND];
__device__ int    g_cand_i[NROWS * NCAND];
__device__ float  g_tw[NROWS * TK];
__device__ int    g_ti[NROWS * TK];
__device__ float  g_emb[NROWS * DD];
__device__ float  g_hatt[NROWS * DH];
__device__ float  g_att[NROWS];
__device__ float  g_a[NROWS];
__device__ float  g_part[NCHUNK * DD];
__device__ float  g_colmean[DD];
// fp16 operand buffers
__device__ __half g_xh[NROWS * DIN];
__device__ __half g_h16[NROWS * DD];
__device__ __half g_eh16[NROWS * DD];
__device__ __half g_et16[NROWS * DD];
__device__ __half g_s1h[NROWS * DD];
__device__ __half g_b1h[NROWS * DD];
__device__ __half g_emb16[NROWS * DD];
// fp16 weights (same [K,N] layout as fp32 originals)
__device__ __half g_fc1_wh[DIN * DD];
__device__ __half g_wh_wh[DD * DD];
__device__ __half g_wt_wh[DD * DD];
__device__ __half g_lin1_wh[DD * DD];
__device__ __half g_lin2_wh[DD * DD];
__device__ __half g_att1_wh[DD * DH];

// ------------------------- cp.async helpers ----------------------------------
__device__ __forceinline__ void cp_async16(void* smem_ptr, const void* gptr) {
    unsigned saddr = (unsigned)__cvta_generic_to_shared(smem_ptr);
    asm volatile("cp.async.cg.shared.global [%0], [%1], 16;\n" :: "r"(saddr), "l"(gptr));
}
__device__ __forceinline__ void cp_commit() { asm volatile("cp.async.commit_group;\n"); }
__device__ __forceinline__ void cp_wait0()  { asm volatile("cp.async.wait_group 0;\n"); }
__device__ __forceinline__ void cp_wait1()  { asm volatile("cp.async.wait_group 1;\n"); }

// ------------------------- fp16 wmma GEMM, 3-stage cp.async pipeline ---------
// Block tile 128(M) x 256(N), BK=32, 256 threads = 8 warps (2x4), 64x64/warp.
// NN: B is [K,Nc] half row-major.  NT: B is [Nc,K] half row-major (C = A@B^T).
// EPI: 0=none, 1=relu, 2=leaky(0.01)
// TOPK: instead of storing C, emit per-row top-6 (value, col) per tile.
#define LDA   40      // halves: 32 + 8 pad
#define LDBN  264     // halves: 256 + 8 pad
#define LDC   68      // floats
#define A_H   (128 * LDA)                    // 5120 halves
#define B_H   10240                           // max(256*LDA=10240, 32*LDBN=8448)
#define STAGE_H (A_H + B_H)                   // 15360 halves = 30720 B
#define NSTAGE 3
#define SMEM_BYTES (NSTAGE * STAGE_H * 2)     // 92160 B

template <bool NT>
__device__ __forceinline__ void load_tiles(__half* As, __half* Bs,
                                           const __half* __restrict__ A,
                                           const __half* __restrict__ B,
                                           int m0, int n0, int k0, int K, int Nc,
                                           int tid) {
    #pragma unroll
    for (int f = tid; f < 512; f += 256) {
        int m = f >> 2, kq = (f & 3) << 3;
        cp_async16(&As[m * LDA + kq], &A[(size_t)(m0 + m) * K + k0 + kq]);
    }
    if (NT) {
        #pragma unroll
        for (int f = tid; f < 1024; f += 256) {
            int n = f >> 2, kq = (f & 3) << 3;
            cp_async16(&Bs[n * LDA + kq], &B[(size_t)(n0 + n) * K + k0 + kq]);
        }
    } else {
        #pragma unroll
        for (int f = tid; f < 1024; f += 256) {
            int k = f >> 5, nq = (f & 31) << 3;
            cp_async16(&Bs[k * LDBN + nq], &B[(size_t)(k0 + k) * Nc + n0 + nq]);
        }
    }
}

template <int EPI, bool NT, bool ACC, bool TOPK>
__global__ __launch_bounds__(256, 1)
void gemm16_kernel(const __half* __restrict__ A, const __half* __restrict__ B,
                   const float* __restrict__ bias, float* __restrict__ C32,
                   __half* __restrict__ C16, int M, int Nc, int K, float alpha,
                   float* __restrict__ cand_v, int* __restrict__ cand_i) {
    extern __shared__ __half smem[];

    const int tid    = threadIdx.x;
    const int warpId = tid >> 5;
    const int warp_m = warpId & 1;
    const int warp_n = warpId >> 1;
    const int m_off  = warp_m * 64;
    const int n_off  = warp_n * 64;
    const int m0 = blockIdx.y * 128;
    const int n0 = blockIdx.x * 256;

    using BLayout = typename std::conditional<NT, wmma::col_major, wmma::row_major>::type;

    wmma::fragment<wmma::accumulator, 16, 16, 16, float> acc[4][4];
    #pragma unroll
    for (int i = 0; i < 4; i++)
        #pragma unroll
        for (int j = 0; j < 4; j++)
            wmma::fill_fragment(acc[i][j], 0.0f);

    const int niter = K / 32;

    load_tiles<NT>(smem, smem + A_H, A, B, m0, n0, 0, K, Nc, tid);
    cp_commit();
    if (niter > 1) {
        __half* s1p = smem + STAGE_H;
        load_tiles<NT>(s1p, s1p + A_H, A, B, m0, n0, 32, K, Nc, tid);
    }
    cp_commit();

    int stage = 0;
    for (int it = 0; it < niter; it++) {
        cp_wait1();
        __syncthreads();

        __half* As = smem + stage * STAGE_H;
        __half* Bs = As + A_H;

        int knext = (it + 2) * 32;
        int nstage = stage + 2; if (nstage >= NSTAGE) nstage -= NSTAGE;
        if (knext < K) {
            __half* An = smem + nstage * STAGE_H;
            load_tiles<NT>(An, An + A_H, A, B, m0, n0, knext, K, Nc, tid);
        }
        cp_commit();

        #pragma unroll
        for (int kk = 0; kk < 2; kk++) {
            wmma::fragment<wmma::matrix_a, 16, 16, 16, __half, wmma::row_major> af[4];
            wmma::fragment<wmma::matrix_b, 16, 16, 16, __half, BLayout> bf[4];
            #pragma unroll
            for (int i = 0; i < 4; i++)
                wmma::load_matrix_sync(af[i], &As[(m_off + i * 16) * LDA + kk * 16], LDA);
            #pragma unroll
            for (int j = 0; j < 4; j++) {
                if (NT)
                    wmma::load_matrix_sync(bf[j], &Bs[(n_off + j * 16) * LDA + kk * 16], LDA);
                else
                    wmma::load_matrix_sync(bf[j], &Bs[kk * 16 * LDBN + n_off + j * 16], LDBN);
            }
            #pragma unroll
            for (int i = 0; i < 4; i++)
                #pragma unroll
                for (int j = 0; j < 4; j++)
                    wmma::mma_sync(acc[i][j], af[i], bf[j], acc[i][j]);
        }

        stage++; if (stage >= NSTAGE) stage = 0;
    }

    cp_wait0();

    float* Cs = (float*)smem;

    // per-thread top-6 state for TOPK path (thread t: row t>>1, half t&1)
    float tv[TK]; int tix[TK];
    if (TOPK) {
        #pragma unroll
        for (int k = 0; k < TK; k++) { tv[k] = -FLT_MAX; tix[k] = 0x7FFFFFFF; }
    }

    #pragma unroll
    for (int h = 0; h < 4; h++) {
        __syncthreads();
        if (warp_n == h) {
            #pragma unroll
            for (int i = 0; i < 4; i++)
                #pragma unroll
                for (int j = 0; j < 4; j++)
                    wmma::store_matrix_sync(&Cs[(m_off + i * 16) * LDC + j * 16],
                                            acc[i][j], LDC, wmma::mem_row_major);
        }
        __syncthreads();
        if (TOPK) {
            int r = tid >> 1, half = tid & 1;
            #pragma unroll 8
            for (int cc = 0; cc < 32; cc++) {
                int c = half * 32 + cc;
                float v = Cs[r * LDC + c] * alpha;
                if (v > tv[TK - 1]) {
                    int n = n0 + h * 64 + c;
                    int pos = TK - 1;
                    #pragma unroll
                    for (int k = TK - 2; k >= 0; k--) {
                        if (v > tv[k]) { tv[k + 1] = tv[k]; tix[k + 1] = tix[k]; pos = k; }
                    }
                    tv[pos] = v; tix[pos] = n;
                }
            }
        } else {
            for (int e = tid; e < 128 * 64; e += 256) {
                int m = e >> 6, c = e & 63;
                int n = n0 + h * 64 + c;
                float v = Cs[m * LDC + c] * alpha;
                if (bias) v += bias[n];
                if (EPI == 1) v = fmaxf(v, 0.0f);
                else if (EPI == 2) v = (v > 0.0f) ? v : 0.01f * v;
                size_t o = (size_t)(m0 + m) * Nc + n;
                if (ACC) v += C32[o];
                if (C32) C32[o] = v;
                if (C16) C16[o] = __float2half(v);
            }
        }
    }

    if (TOPK) {
        // merge the 2 half-row lists and write 6 candidates per row
        __syncthreads();
        float* sv = (float*)smem;            // 256*6 floats
        int*   si = (int*)(sv + 256 * TK);   // 256*6 ints
        #pragma unroll
        for (int k = 0; k < TK; k++) { sv[tid * TK + k] = tv[k]; si[tid * TK + k] = tix[k]; }
        __syncthreads();
        if ((tid & 1) == 0) {
            int r = tid >> 1;
            const float* bvv = &sv[(tid + 1) * TK];
            const int*   bii = &si[(tid + 1) * TK];
            float rv[TK]; int ri[TK];
            int ia = 0, ib = 0;
            #pragma unroll
            for (int k = 0; k < TK; k++) {
                float va = tv[ia], vb = bvv[ib];
                bool takeA = (va > vb) || (va == vb && tix[ia] <= bii[ib]);
                if (takeA) { rv[k] = va; ri[k] = tix[ia]; ia++; }
                else       { rv[k] = vb; ri[k] = bii[ib]; ib++; }
            }
            size_t base = (size_t)(m0 + r) * NCAND + blockIdx.x * TK;
            #pragma unroll
            for (int k = 0; k < TK; k++) { cand_v[base + k] = rv[k]; cand_i[base + k] = ri[k]; }
        }
    }
}

// ------------------------- candidate reduce: 192 -> top-6 per row ------------
__global__ void topk_reduce_kernel(const float* __restrict__ cand_v,
                                   const int* __restrict__ cand_i,
                                   float* __restrict__ tw, int* __restrict__ ti) {
    const unsigned FULL = 0xFFFFFFFFu;
    int warp = threadIdx.x >> 5;
    int lane = threadIdx.x & 31;
    int row = blockIdx.x * 8 + warp;
    const float* cv = cand_v + (size_t)row * NCAND;
    const int*   ci = cand_i + (size_t)row * NCAND;

    float val[TK]; int idx[TK];
    #pragma unroll
    for (int k = 0; k < TK; k++) { val[k] = -FLT_MAX; idx[k] = 0x7FFFFFFF; }

    #pragma unroll
    for (int j = 0; j < TK; j++) {
        int p = lane + j * 32;
        float v = cv[p]; int ii = ci[p];
        if (v > val[TK - 1] || (v == val[TK - 1] && ii < idx[TK - 1])) {
            int pos = TK - 1;
            #pragma unroll
            for (int k = TK - 2; k >= 0; k--) {
                if (v > val[k] || (v == val[k] && ii < idx[k])) {
                    val[k + 1] = val[k]; idx[k + 1] = idx[k]; pos = k;
                }
            }
            val[pos] = v; idx[pos] = ii;
        }
    }

    int head = 0;
    for (int r = 0; r < TK; r++) {
        float bv = (head < TK) ? val[head] : -FLT_MAX;
        int   bi = (head < TK) ? idx[head] : 0x7FFFFFFF;
        int   bl = lane;
        #pragma unroll
        for (int off = 16; off > 0; off >>= 1) {
            float ov = __shfl_down_sync(FULL, bv, off);
            int   oi = __shfl_down_sync(FULL, bi, off);
            int   ol = __shfl_down_sync(FULL, bl, off);
            if (ov > bv || (ov == bv && oi < bi)) { bv = ov; bi = oi; bl = ol; }
        }
        bv = __shfl_sync(FULL, bv, 0);
        bi = __shfl_sync(FULL, bi, 0);
        bl = __shfl_sync(FULL, bl, 0);
        if (lane == 0) { tw[row * TK + r] = bv; ti[row * TK + r] = bi; }
        if (lane == bl) head++;
    }
}

// ------------------------- conversion kernel ----------------------------------
__global__ void conv_half_kernel(const float* __restrict__ X, __half* __restrict__ Xh) {
    int i = (blockIdx.x * blockDim.x + threadIdx.x) * 4;
    float4 v = *reinterpret_cast<const float4*>(&X[i]);
    *reinterpret_cast<__half2*>(&Xh[i])     = __floats2half2_rn(v.x, v.y);
    *reinterpret_cast<__half2*>(&Xh[i + 2]) = __floats2half2_rn(v.z, v.w);
}

// ------------------------- column sum (optionally row-weighted) --------------
__global__ void colsum_partial(const float* __restrict__ X,
                               const float* __restrict__ w,
                               float* __restrict__ part) {
    int d = threadIdx.x;
    int r0 = blockIdx.x * ROWS_PER_CHUNK;
    float s = 0.0f;
    for (int r = 0; r < ROWS_PER_CHUNK; r++) {
        float v = X[(size_t)(r0 + r) * DD + d];
        if (w) v *= w[r0 + r];
        s += v;
    }
    part[blockIdx.x * DD + d] = s;
}

__global__ void colmean_finish(const float* __restrict__ part, float* __restrict__ mean) {
    int d = threadIdx.x;
    float s = 0.0f;
    for (int c = 0; c < NCHUNK; c++) s += part[c * DD + d];
    mean[d] = s / (float)NROWS;
}

__global__ void mean_update(const float* __restrict__ h32, const float* __restrict__ mean,
                            __half* __restrict__ h16) {
    int i = blockIdx.x * blockDim.x + threadIdx.x;
    h16[i] = __float2half((h32[i] + mean[i & (DD - 1)]) * 0.5f);
}

// ------------------------- per-row neighbor aggregation ----------------------
__global__ __launch_bounds__(256)
void aggregate_kernel(const float* __restrict__ eh, const float* __restrict__ et,
                      const float* __restrict__ tw, const int* __restrict__ ti,
                      __half* __restrict__ s1h, __half* __restrict__ b1h) {
    __shared__ float red[256];
    __shared__ float sh_ka[TK];
    int row = blockIdx.x;
    int t = threadIdx.x;

    float p[TK];
    {
        float mx = -FLT_MAX;
        #pragma unroll
        for (int k = 0; k < TK; k++) { p[k] = tw[row * TK + k]; mx = fmaxf(mx, p[k]); }
        float s = 0.0f;
        #pragma unroll
        for (int k = 0; k < TK; k++) { p[k] = expf(p[k] - mx); s += p[k]; }
        #pragma unroll
        for (int k = 0; k < TK; k++) p[k] /= s;
    }

    float eh0 = eh[(size_t)row * DD + t];
    float eh1 = eh[(size_t)row * DD + t + 256];
    float Nb[TK][2];

    for (int k = 0; k < TK; k++) {
        int j = ti[row * TK + k];
        Nb[k][0] = et[(size_t)j * DD + t];
        Nb[k][1] = et[(size_t)j * DD + t + 256];
        float g0 = tanhf(fmaf(2.0f - p[k], eh0, p[k] * Nb[k][0]));
        float g1 = tanhf(fmaf(2.0f - p[k], eh1, p[k] * Nb[k][1]));
        float partial = Nb[k][0] * g0 + Nb[k][1] * g1;
        red[t] = partial; __syncthreads();
        for (int s = 128; s > 0; s >>= 1) {
            if (t < s) red[t] += red[t + s];
            __syncthreads();
        }
        if (t == 0) sh_ka[k] = red[0];
        __syncthreads();
    }

    float kp[TK];
    {
        float mx = -FLT_MAX;
        #pragma unroll
        for (int k = 0; k < TK; k++) { kp[k] = sh_ka[k]; mx = fmaxf(mx, kp[k]); }
        float s = 0.0f;
        #pragma unroll
        for (int k = 0; k < TK; k++) { kp[k] = expf(kp[k] - mx); s += kp[k]; }
        #pragma unroll
        for (int k = 0; k < TK; k++) kp[k] /= s;
    }

    float en0 = 0.0f, en1 = 0.0f;
    #pragma unroll
    for (int k = 0; k < TK; k++) { en0 = fmaf(kp[k], Nb[k][0], en0); en1 = fmaf(kp[k], Nb[k][1], en1); }

    s1h[(size_t)row * DD + t]       = __float2half(eh0 + en0);
    s1h[(size_t)row * DD + t + 256] = __float2half(eh1 + en1);
    b1h[(size_t)row * DD + t]       = __float2half(eh0 * en0);
    b1h[(size_t)row * DD + t + 256] = __float2half(eh1 * en1);
}

// ------------------------- attention readout ---------------------------------
__global__ void att_mv_kernel(const float* __restrict__ hatt,
                              const float* __restrict__ w2, const float* __restrict__ b2,
                              float* __restrict__ att) {
    const unsigned FULL = 0xFFFFFFFFu;
    int warp = threadIdx.x >> 5;
    int lane = threadIdx.x & 31;
    int row = blockIdx.x * 8 + warp;
    float s = 0.0f;
    for (int d = lane; d < DH; d += 32)
        s = fmaf(hatt[(size_t)row * DH + d], w2[d], s);
    #pragma unroll
    for (int off = 16; off > 0; off >>= 1) s += __shfl_down_sync(FULL, s, off);
    if (lane == 0) att[row] = s + b2[0];
}

__global__ void softmax_n_kernel(const float* __restrict__ att, float* __restrict__ a) {
    __shared__ float red[1024];
    __shared__ float s_max, s_sum;
    int t = threadIdx.x;
    float lm = -FLT_MAX;
    for (int i = t; i < NROWS; i += 1024) lm = fmaxf(lm, att[i]);
    red[t] = lm; __syncthreads();
    for (int s = 512; s > 0; s >>= 1) { if (t < s) red[t] = fmaxf(red[t], red[t + s]); __syncthreads(); }
    if (t == 0) s_max = red[0];
    __syncthreads();
    float ls = 0.0f;
    for (int i = t; i < NROWS; i += 1024) ls += expf(att[i] - s_max);
    red[t] = ls; __syncthreads();
    for (int s = 512; s > 0; s >>= 1) { if (t < s) red[t] += red[t + s]; __syncthreads(); }
    if (t == 0) s_sum = red[0];
    __syncthreads();
    float inv = 1.0f / s_sum;
    for (int i = t; i < NROWS; i += 1024) a[i] = expf(att[i] - s_max) * inv;
}

// ------------------------- final: LN + fc + softmax + argmax -----------------
__global__ void final_kernel(const float* __restrict__ part,
                             const float* __restrict__ ln_g, const float* __restrict__ ln_b,
                             const float* __restrict__ fc_w, const float* __restrict__ fc_b,
                             float* __restrict__ out, int out_size) {
    __shared__ float red[DD];
    int d = threadIdx.x;
    float pooled = 0.0f;
    for (int c = 0; c < NCHUNK; c++) pooled += part[c * DD + d];

    red[d] = pooled; __syncthreads();
    for (int s = 256; s > 0; s >>= 1) { if (d < s) red[d] += red[d + s]; __syncthreads(); }
    float mu = red[0] / (float)DD;
    __syncthreads();

    float cen = pooled - mu;
    red[d] = cen * cen; __syncthreads();
    for (int s = 256; s > 0; s >>= 1) { if (d < s) red[d] += red[d + s]; __syncthreads(); }
    float var = red[0] / (float)DD;
    __syncthreads();

    float ln = cen * rsqrtf(var + LN_EPS) * ln_g[d] + ln_b[d];

    red[d] = ln * fc_w[2 * d + 0]; __syncthreads();
    for (int s = 256; s > 0; s >>= 1) { if (d < s) red[d] += red[d + s]; __syncthreads(); }
    float o0 = red[0] + fc_b[0];
    __syncthreads();

    red[d] = ln * fc_w[2 * d + 1]; __syncthreads();
    for (int s = 256; s > 0; s >>= 1) { if (d < s) red[d] += red[d + s]; __syncthreads(); }
    float o1 = red[0] + fc_b[1];

    if (d == 0) {
        float m = fmaxf(o0, o1);
        float e0 = expf(o0 - m), e1 = expf(o1 - m);
        float inv = 1.0f / (e0 + e1);
        if (out_size > 0) out[0] = o0;
        if (out_size > 1) out[1] = o1;
        if (out_size > 2) out[2] = e0 * inv;
        if (out_size > 3) out[3] = e1 * inv;
        if (out_size > 4) out[4] = (o1 > o0) ? 1.0f : 0.0f;
    }
}

// ------------------------- host orchestration --------------------------------
static void* symv(const void* s) {
    void* p = nullptr;
    cudaGetSymbolAddress(&p, s);
    return p;
}

template <int EPI, bool NT, bool ACC, bool TOPK>
static void launch_gemm16(const __half* A, const __half* B, const float* bias,
                          float* C32, __half* C16, int M, int Nc, int K, float alpha,
                          float* cv = nullptr, int* ci = nullptr) {
    static bool attr_done = false;
    if (!attr_done) {
        cudaFuncSetAttribute(gemm16_kernel<EPI, NT, ACC, TOPK>,
                             cudaFuncAttributeMaxDynamicSharedMemorySize, SMEM_BYTES);
        attr_done = true;
    }
    gemm16_kernel<EPI, NT, ACC, TOPK><<<dim3(Nc / 256, M / 128), 256, SMEM_BYTES>>>(
        A, B, bias, C32, C16, M, Nc, K, alpha, cv, ci);
}

extern "C" void kernel_launch(void* const* d_in, const int* in_sizes, int n_in,
                              void* d_out, int out_size) {
    const float* x      = (const float*)d_in[0];
    const float* fc1_w  = (const float*)d_in[1];
    const float* fc1_b  = (const float*)d_in[2];
    const float* wh_w   = (const float*)d_in[3];
    const float* wh_b   = (const float*)d_in[4];
    const float* wt_w   = (const float*)d_in[5];
    const float* wt_b   = (const float*)d_in[6];
    const float* lin1_w = (const float*)d_in[7];
    const float* lin1_b = (const float*)d_in[8];
    const float* lin2_w = (const float*)d_in[9];
    const float* lin2_b = (const float*)d_in[10];
    const float* att1_w = (const float*)d_in[11];
    const float* att1_b = (const float*)d_in[12];
    const float* att2_w = (const float*)d_in[13];
    const float* att2_b = (const float*)d_in[14];
    const float* ln_g   = (const float*)d_in[15];
    const float* ln_b   = (const float*)d_in[16];
    const float* fc_w   = (const float*)d_in[17];
    const float* fc_b   = (const float*)d_in[18];

    float*  h      = (float*)symv(g_h);
    float*  eh     = (float*)symv(g_eh);
    float*  et     = (float*)symv(g_et);
    float*  cv     = (float*)symv(g_cand_v);
    int*    ci     = (int*)symv(g_cand_i);
    float*  tw     = (float*)symv(g_tw);
    int*    ti     = (int*)symv(g_ti);
    float*  emb    = (float*)symv(g_emb);
    float*  hatt   = (float*)symv(g_hatt);
    float*  att    = (float*)symv(g_att);
    float*  a      = (float*)symv(g_a);
    float*  part   = (float*)symv(g_part);
    float*  cmean  = (float*)symv(g_colmean);
    __half* xh     = (__half*)symv(g_xh);
    __half* h16    = (__half*)symv(g_h16);
    __half* eh16   = (__half*)symv(g_eh16);
    __half* et16   = (__half*)symv(g_et16);
    __half* s1h    = (__half*)symv(g_s1h);
    __half* b1h    = (__half*)symv(g_b1h);
    __half* emb16  = (__half*)symv(g_emb16);
    __half* fc1_wh = (__half*)symv(g_fc1_wh);
    __half* wh_wh  = (__half*)symv(g_wh_wh);
    __half* wt_wh  = (__half*)symv(g_wt_wh);
    __half* lin1_wh= (__half*)symv(g_lin1_wh);
    __half* lin2_wh= (__half*)symv(g_lin2_wh);
    __half* att1_wh= (__half*)symv(g_att1_wh);

    // 0) fp16 conversions
    conv_half_kernel<<<(NROWS * DIN) / 1024, 256>>>(x, xh);
    conv_half_kernel<<<(DIN * DD) / 1024, 256>>>(fc1_w, fc1_wh);
    conv_half_kernel<<<(DD * DD) / 1024, 256>>>(wh_w, wh_wh);
    conv_half_kernel<<<(DD * DD) / 1024, 256>>>(wt_w, wt_wh);
    conv_half_kernel<<<(DD * DD) / 1024, 256>>>(lin1_w, lin1_wh);
    conv_half_kernel<<<(DD * DD) / 1024, 256>>>(lin2_w, lin2_wh);
    conv_half_kernel<<<(DD * DH) / 1024, 256>>>(att1_w, att1_wh);

    // 1) h = relu(x @ fc1_w + fc1_b)
    launch_gemm16<1, false, false, false>(xh, fc1_wh, fc1_b, h, nullptr, NROWS, DD, DIN, 1.0f);

    // 2) h16 = half((h + colmean(h)) * 0.5)
    colsum_partial<<<NCHUNK, DD>>>(h, nullptr, part);
    colmean_finish<<<1, DD>>>(part, cmean);
    mean_update<<<(NROWS * DD) / 256, 256>>>(h, cmean, h16);

    // 3) e_h, e_t (fp32 + fp16 copies)
    launch_gemm16<0, false, false, false>(h16, wh_wh, wh_b, eh, eh16, NROWS, DD, DD, 1.0f);
    launch_gemm16<0, false, false, false>(h16, wt_wh, wt_b, et, et16, NROWS, DD, DD, 1.0f);

    // 4+5) logits GEMM fused with per-tile top-6 -> candidates -> reduce
    launch_gemm16<0, true, false, true>(eh16, et16, nullptr, nullptr, nullptr,
                                        NROWS, NROWS, DD, SCALE_LOGITS, cv, ci);
    topk_reduce_kernel<<<NROWS / 8, 256>>>(cv, ci, tw, ti);

    // 6) neighbor aggregation -> s1h, b1h
    aggregate_kernel<<<NROWS, 256>>>(eh, et, tw, ti, s1h, b1h);

    // 7) emb = leaky(s1@lin1+b) + leaky(b1@lin2+b)
    launch_gemm16<2, false, false, false>(s1h, lin1_wh, lin1_b, emb, nullptr, NROWS, DD, DD, 1.0f);
    launch_gemm16<2, false, true,  false>(b1h, lin2_wh, lin2_b, emb, emb16, NROWS, DD, DD, 1.0f);

    // 8) attention readout
    launch_gemm16<2, false, false, false>(emb16, att1_wh, att1_b, hatt, nullptr, NROWS, DH, DD, 1.0f);
    att_mv_kernel<<<NROWS / 8, 256>>>(hatt, att2_w, att2_b, att);
    softmax_n_kernel<<<1, 1024>>>(att, a);

    // 9) pooled = sum_i a_i * emb_i
    colsum_partial<<<NCHUNK, DD>>>(emb, a, part);

    // 10) LN + fc + softmax + argmax
    final_kernel<<<1, DD>>>(part, ln_g, ln_b, fc_w, fc_b, (float*)d_out, out_size);
}

// round 8
// speedup vs baseline: 1.3197x; 1.3197x over previous
#include <cuda_runtime.h>
#include <cuda_fp16.h>
#include <mma.h>
#include <math.h>
#include <float.h>
#include <stdint.h>
#include <type_traits>

using namespace nvcuda;

#define NROWS 8192
#define DIN   1024
#define DD    512
#define DH    256      // D/2
#define TK    6
#define NCHUNK 64
#define ROWS_PER_CHUNK (NROWS / NCHUNK)
#define LN_EPS 1e-5f
#define SCALE_LOGITS 0.044194173824159216f  // 512^-0.5

// ------------------------- scratch (device globals; no cudaMalloc allowed) ---
__device__ float  g_h[NROWS * DD];
__device__ __half g_logits16[(size_t)NROWS * NROWS];  // 128 MB
__device__ float  g_tw[NROWS * TK];
__device__ int    g_ti[NROWS * TK];
__device__ float  g_emb[NROWS * DD];
__device__ float  g_hatt[NROWS * DH];
__device__ float  g_att[NROWS];
__device__ float  g_a[NROWS];
__device__ float  g_part[NCHUNK * DD];
__device__ float  g_colmean[DD];
// fp16 operand buffers
__device__ __half g_xh[NROWS * DIN];
__device__ __half g_h16[NROWS * DD];
__device__ __half g_eh16[NROWS * DD];
__device__ __half g_et16[NROWS * DD];
__device__ __half g_s1h[NROWS * DD];
__device__ __half g_b1h[NROWS * DD];
__device__ __half g_emb16[NROWS * DD];
// fp16 weights (same [K,N] layout as fp32 originals)
__device__ __half g_fc1_wh[DIN * DD];
__device__ __half g_wh_wh[DD * DD];
__device__ __half g_wt_wh[DD * DD];
__device__ __half g_lin1_wh[DD * DD];
__device__ __half g_lin2_wh[DD * DD];
__device__ __half g_att1_wh[DD * DH];

// ------------------------- cp.async helpers ----------------------------------
__device__ __forceinline__ void cp_async16(void* smem_ptr, const void* gptr) {
    unsigned saddr = (unsigned)__cvta_generic_to_shared(smem_ptr);
    asm volatile("cp.async.cg.shared.global [%0], [%1], 16;\n" :: "r"(saddr), "l"(gptr));
}
__device__ __forceinline__ void cp_commit() { asm volatile("cp.async.commit_group;\n"); }
__device__ __forceinline__ void cp_wait0()  { asm volatile("cp.async.wait_group 0;\n"); }
__device__ __forceinline__ void cp_wait1()  { asm volatile("cp.async.wait_group 1;\n"); }

// ------------------------- fp16 wmma GEMM, 3-stage cp.async pipeline ---------
// Block tile 128(M) x 256(N), BK=32, 256 threads = 8 warps (2x4), 64x64/warp.
// NN: B is [K,Nc] half row-major.  NT: B is [Nc,K] half row-major (C = A@B^T).
// EPI: 0=none, 1=relu, 2=leaky(0.01)
#define LDA   40      // halves: 32 + 8 pad
#define LDBN  264     // halves: 256 + 8 pad
#define LDC   68      // floats
#define A_H   (128 * LDA)                    // 5120 halves
#define B_H   10240                           // max(256*LDA, 32*LDBN)
#define STAGE_H (A_H + B_H)                   // 15360 halves = 30720 B
#define NSTAGE 3
#define SMEM_BYTES (NSTAGE * STAGE_H * 2)     // 92160 B

template <bool NT>
__device__ __forceinline__ void load_tiles(__half* As, __half* Bs,
                                           const __half* __restrict__ A,
                                           const __half* __restrict__ B,
                                           int m0, int n0, int k0, int K, int Nc,
                                           int tid) {
    #pragma unroll
    for (int f = tid; f < 512; f += 256) {
        int m = f >> 2, kq = (f & 3) << 3;
        cp_async16(&As[m * LDA + kq], &A[(size_t)(m0 + m) * K + k0 + kq]);
    }
    if (NT) {
        #pragma unroll
        for (int f = tid; f < 1024; f += 256) {
            int n = f >> 2, kq = (f & 3) << 3;
            cp_async16(&Bs[n * LDA + kq], &B[(size_t)(n0 + n) * K + k0 + kq]);
        }
    } else {
        #pragma unroll
        for (int f = tid; f < 1024; f += 256) {
            int k = f >> 5, nq = (f & 31) << 3;
            cp_async16(&Bs[k * LDBN + nq], &B[(size_t)(k0 + k) * Nc + n0 + nq]);
        }
    }
}

template <int EPI, bool NT, bool ACC>
__global__ __launch_bounds__(256, 1)
void gemm16_kernel(const __half* __restrict__ A, const __half* __restrict__ B,
                   const float* __restrict__ bias, float* __restrict__ C32,
                   __half* __restrict__ C16, int M, int Nc, int K, float alpha) {
    extern __shared__ __half smem[];

    const int tid    = threadIdx.x;
    const int warpId = tid >> 5;
    const int warp_m = warpId & 1;
    const int warp_n = warpId >> 1;
    const int m_off  = warp_m * 64;
    const int n_off  = warp_n * 64;
    const int m0 = blockIdx.y * 128;
    const int n0 = blockIdx.x * 256;

    using BLayout = typename std::conditional<NT, wmma::col_major, wmma::row_major>::type;

    wmma::fragment<wmma::accumulator, 16, 16, 16, float> acc[4][4];
    #pragma unroll
    for (int i = 0; i < 4; i++)
        #pragma unroll
        for (int j = 0; j < 4; j++)
            wmma::fill_fragment(acc[i][j], 0.0f);

    const int niter = K / 32;

    load_tiles<NT>(smem, smem + A_H, A, B, m0, n0, 0, K, Nc, tid);
    cp_commit();
    if (niter > 1) {
        __half* s1p = smem + STAGE_H;
        load_tiles<NT>(s1p, s1p + A_H, A, B, m0, n0, 32, K, Nc, tid);
    }
    cp_commit();

    int stage = 0;
    for (int it = 0; it < niter; it++) {
        cp_wait1();
        __syncthreads();

        __half* As = smem + stage * STAGE_H;
        __half* Bs = As + A_H;

        int knext = (it + 2) * 32;
        int nstage = stage + 2; if (nstage >= NSTAGE) nstage -= NSTAGE;
        if (knext < K) {
            __half* An = smem + nstage * STAGE_H;
            load_tiles<NT>(An, An + A_H, A, B, m0, n0, knext, K, Nc, tid);
        }
        cp_commit();

        #pragma unroll
        for (int kk = 0; kk < 2; kk++) {
            wmma::fragment<wmma::matrix_a, 16, 16, 16, __half, wmma::row_major> af[4];
            wmma::fragment<wmma::matrix_b, 16, 16, 16, __half, BLayout> bf[4];
            #pragma unroll
            for (int i = 0; i < 4; i++)
                wmma::load_matrix_sync(af[i], &As[(m_off + i * 16) * LDA + kk * 16], LDA);
            #pragma unroll
            for (int j = 0; j < 4; j++) {
                if (NT)
                    wmma::load_matrix_sync(bf[j], &Bs[(n_off + j * 16) * LDA + kk * 16], LDA);
                else
                    wmma::load_matrix_sync(bf[j], &Bs[kk * 16 * LDBN + n_off + j * 16], LDBN);
            }
            #pragma unroll
            for (int i = 0; i < 4; i++)
                #pragma unroll
                for (int j = 0; j < 4; j++)
                    wmma::mma_sync(acc[i][j], af[i], bf[j], acc[i][j]);
        }

        stage++; if (stage >= NSTAGE) stage = 0;
    }

    cp_wait0();

    float* Cs = (float*)smem;
    #pragma unroll
    for (int h = 0; h < 4; h++) {
        __syncthreads();
        if (warp_n == h) {
            #pragma unroll
            for (int i = 0; i < 4; i++)
                #pragma unroll
                for (int j = 0; j < 4; j++)
                    wmma::store_matrix_sync(&Cs[(m_off + i * 16) * LDC + j * 16],
                                            acc[i][j], LDC, wmma::mem_row_major);
        }
        __syncthreads();
        for (int e = tid; e < 128 * 64; e += 256) {
            int m = e >> 6, c = e & 63;
            int n = n0 + h * 64 + c;
            float v = Cs[m * LDC + c] * alpha;
            if (bias) v += bias[n];
            if (EPI == 1) v = fmaxf(v, 0.0f);
            else if (EPI == 2) v = (v > 0.0f) ? v : 0.01f * v;
            size_t o = (size_t)(m0 + m) * Nc + n;
            if (ACC) v += C32[o];
            if (C32) C32[o] = v;
            if (C16) C16[o] = __float2half(v);
        }
    }
}

// ------------------------- conversion kernel ----------------------------------
__global__ void conv_half_kernel(const float* __restrict__ X, __half* __restrict__ Xh) {
    int i = (blockIdx.x * blockDim.x + threadIdx.x) * 4;
    float4 v = *reinterpret_cast<const float4*>(&X[i]);
    *reinterpret_cast<__half2*>(&Xh[i])     = __floats2half2_rn(v.x, v.y);
    *reinterpret_cast<__half2*>(&Xh[i + 2]) = __floats2half2_rn(v.z, v.w);
}

// ------------------------- column sum (optionally row-weighted) --------------
__global__ void colsum_partial(const float* __restrict__ X,
                               const float* __restrict__ w,
                               float* __restrict__ part) {
    int d = threadIdx.x;
    int r0 = blockIdx.x * ROWS_PER_CHUNK;
    float s = 0.0f;
    for (int r = 0; r < ROWS_PER_CHUNK; r++) {
        float v = X[(size_t)(r0 + r) * DD + d];
        if (w) v *= w[r0 + r];
        s += v;
    }
    part[blockIdx.x * DD + d] = s;
}

__global__ void colmean_finish(const float* __restrict__ part, float* __restrict__ mean) {
    int d = threadIdx.x;
    float s = 0.0f;
    for (int c = 0; c < NCHUNK; c++) s += part[c * DD + d];
    mean[d] = s / (float)NROWS;
}

__global__ void mean_update(const float* __restrict__ h32, const float* __restrict__ mean,
                            __half* __restrict__ h16) {
    int i = blockIdx.x * blockDim.x + threadIdx.x;
    h16[i] = __float2half((h32[i] + mean[i & (DD - 1)]) * 0.5f);
}

// ------------------------- top-6 per row (warp/row, vectorized fp16) ---------
__global__ void topk_kernel(const __half* __restrict__ logits,
                            float* __restrict__ tw, int* __restrict__ ti) {
    const unsigned FULL = 0xFFFFFFFFu;
    int warp = threadIdx.x >> 5;
    int lane = threadIdx.x & 31;
    int row = blockIdx.x * 8 + warp;

    const __half* rp = logits + (size_t)row * NROWS;

    float val[TK];
    int   idx[TK];
    #pragma unroll
    for (int k = 0; k < TK; k++) { val[k] = -FLT_MAX; idx[k] = 0x7FFFFFFF; }

    // 8 halves per lane per iter; warp covers 256 contiguous halves (512 B)
    for (int it = 0; it < NROWS / 256; it++) {
        int jbase = it * 256 + lane * 8;
        uint4 pkt = *reinterpret_cast<const uint4*>(rp + jbase);
        const __half* hp = reinterpret_cast<const __half*>(&pkt);
        #pragma unroll
        for (int e = 0; e < 8; e++) {
            float v = __half2float(hp[e]);
            if (v > val[TK - 1]) {
                int j = jbase + e;
                int pos = TK - 1;
                #pragma unroll
                for (int k = TK - 2; k >= 0; k--) {
                    if (v > val[k]) { val[k + 1] = val[k]; idx[k + 1] = idx[k]; pos = k; }
                }
                val[pos] = v; idx[pos] = j;
            }
        }
    }

    int head = 0;
    for (int r = 0; r < TK; r++) {
        float bv = (head < TK) ? val[head] : -FLT_MAX;
        int   bi = (head < TK) ? idx[head] : 0x7FFFFFFF;
        int   bl = lane;
        #pragma unroll
        for (int off = 16; off > 0; off >>= 1) {
            float ov = __shfl_down_sync(FULL, bv, off);
            int   oi = __shfl_down_sync(FULL, bi, off);
            int   ol = __shfl_down_sync(FULL, bl, off);
            if (ov > bv || (ov == bv && oi < bi)) { bv = ov; bi = oi; bl = ol; }
        }
        bv = __shfl_sync(FULL, bv, 0);
        bi = __shfl_sync(FULL, bi, 0);
        bl = __shfl_sync(FULL, bl, 0);
        if (lane == 0) { tw[row * TK + r] = bv; ti[row * TK + r] = bi; }
        if (lane == bl) head++;
    }
}

// ------------------------- per-row neighbor aggregation (fp16 inputs) --------
__global__ __launch_bounds__(256)
void aggregate_kernel(const __half* __restrict__ eh16, const __half* __restrict__ et16,
                      const float* __restrict__ tw, const int* __restrict__ ti,
                      __half* __restrict__ s1h, __half* __restrict__ b1h) {
    __shared__ float red[256];
    __shared__ float sh_ka[TK];
    int row = blockIdx.x;
    int t = threadIdx.x;

    float p[TK];
    {
        float mx = -FLT_MAX;
        #pragma unroll
        for (int k = 0; k < TK; k++) { p[k] = tw[row * TK + k]; mx = fmaxf(mx, p[k]); }
        float s = 0.0f;
        #pragma unroll
        for (int k = 0; k < TK; k++) { p[k] = expf(p[k] - mx); s += p[k]; }
        #pragma unroll
        for (int k = 0; k < TK; k++) p[k] /= s;
    }

    float eh0 = __half2float(eh16[(size_t)row * DD + t]);
    float eh1 = __half2float(eh16[(size_t)row * DD + t + 256]);
    float Nb[TK][2];

    for (int k = 0; k < TK; k++) {
        int j = ti[row * TK + k];
        Nb[k][0] = __half2float(et16[(size_t)j * DD + t]);
        Nb[k][1] = __half2float(et16[(size_t)j * DD + t + 256]);
        float g0 = tanhf(fmaf(2.0f - p[k], eh0, p[k] * Nb[k][0]));
        float g1 = tanhf(fmaf(2.0f - p[k], eh1, p[k] * Nb[k][1]));
        float partial = Nb[k][0] * g0 + Nb[k][1] * g1;
        red[t] = partial; __syncthreads();
        for (int s = 128; s > 0; s >>= 1) {
            if (t < s) red[t] += red[t + s];
            __syncthreads();
        }
        if (t == 0) sh_ka[k] = red[0];
        __syncthreads();
    }

    float kp[TK];
    {
        float mx = -FLT_MAX;
        #pragma unroll
        for (int k = 0; k < TK; k++) { kp[k] = sh_ka[k]; mx = fmaxf(mx, kp[k]); }
        float s = 0.0f;
        #pragma unroll
        for (int k = 0; k < TK; k++) { kp[k] = expf(kp[k] - mx); s += kp[k]; }
        #pragma unroll
        for (int k = 0; k < TK; k++) kp[k] /= s;
    }

    float en0 = 0.0f, en1 = 0.0f;
    #pragma unroll
    for (int k = 0; k < TK; k++) { en0 = fmaf(kp[k], Nb[k][0], en0); en1 = fmaf(kp[k], Nb[k][1], en1); }

    s1h[(size_t)row * DD + t]       = __float2half(eh0 + en0);
    s1h[(size_t)row * DD + t + 256] = __float2half(eh1 + en1);
    b1h[(size_t)row * DD + t]       = __float2half(eh0 * en0);
    b1h[(size_t)row * DD + t + 256] = __float2half(eh1 * en1);
}

// ------------------------- attention readout ---------------------------------
__global__ void att_mv_kernel(const float* __restrict__ hatt,
                              const float* __restrict__ w2, const float* __restrict__ b2,
                              float* __restrict__ att) {
    const unsigned FULL = 0xFFFFFFFFu;
    int warp = threadIdx.x >> 5;
    int lane = threadIdx.x & 31;
    int row = blockIdx.x * 8 + warp;
    float s = 0.0f;
    for (int d = lane; d < DH; d += 32)
        s = fmaf(hatt[(size_t)row * DH + d], w2[d], s);
    #pragma unroll
    for (int off = 16; off > 0; off >>= 1) s += __shfl_down_sync(FULL, s, off);
    if (lane == 0) att[row] = s + b2[0];
}

__global__ void softmax_n_kernel(const float* __restrict__ att, float* __restrict__ a) {
    __shared__ float red[1024];
    __shared__ float s_max, s_sum;
    int t = threadIdx.x;
    float lm = -FLT_MAX;
    for (int i = t; i < NROWS; i += 1024) lm = fmaxf(lm, att[i]);
    red[t] = lm; __syncthreads();
    for (int s = 512; s > 0; s >>= 1) { if (t < s) red[t] = fmaxf(red[t], red[t + s]); __syncthreads(); }
    if (t == 0) s_max = red[0];
    __syncthreads();
    float ls = 0.0f;
    for (int i = t; i < NROWS; i += 1024) ls += expf(att[i] - s_max);
    red[t] = ls; __syncthreads();
    for (int s = 512; s > 0; s >>= 1) { if (t < s) red[t] += red[t + s]; __syncthreads(); }
    if (t == 0) s_sum = red[0];
    __syncthreads();
    float inv = 1.0f / s_sum;
    for (int i = t; i < NROWS; i += 1024) a[i] = expf(att[i] - s_max) * inv;
}

// ------------------------- final: LN + fc + softmax + argmax -----------------
__global__ void final_kernel(const float* __restrict__ part,
                             const float* __restrict__ ln_g, const float* __restrict__ ln_b,
                             const float* __restrict__ fc_w, const float* __restrict__ fc_b,
                             float* __restrict__ out, int out_size) {
    __shared__ float red[DD];
    int d = threadIdx.x;
    float pooled = 0.0f;
    for (int c = 0; c < NCHUNK; c++) pooled += part[c * DD + d];

    red[d] = pooled; __syncthreads();
    for (int s = 256; s > 0; s >>= 1) { if (d < s) red[d] += red[d + s]; __syncthreads(); }
    float mu = red[0] / (float)DD;
    __syncthreads();

    float cen = pooled - mu;
    red[d] = cen * cen; __syncthreads();
    for (int s = 256; s > 0; s >>= 1) { if (d < s) red[d] += red[d + s]; __syncthreads(); }
    float var = red[0] / (float)DD;
    __syncthreads();

    float ln = cen * rsqrtf(var + LN_EPS) * ln_g[d] + ln_b[d];

    red[d] = ln * fc_w[2 * d + 0]; __syncthreads();
    for (int s = 256; s > 0; s >>= 1) { if (d < s) red[d] += red[d + s]; __syncthreads(); }
    float o0 = red[0] + fc_b[0];
    __syncthreads();

    red[d] = ln * fc_w[2 * d + 1]; __syncthreads();
    for (int s = 256; s > 0; s >>= 1) { if (d < s) red[d] += red[d + s]; __syncthreads(); }
    float o1 = red[0] + fc_b[1];

    if (d == 0) {
        float m = fmaxf(o0, o1);
        float e0 = expf(o0 - m), e1 = expf(o1 - m);
        float inv = 1.0f / (e0 + e1);
        if (out_size > 0) out[0] = o0;
        if (out_size > 1) out[1] = o1;
        if (out_size > 2) out[2] = e0 * inv;
        if (out_size > 3) out[3] = e1 * inv;
        if (out_size > 4) out[4] = (o1 > o0) ? 1.0f : 0.0f;
    }
}

// ------------------------- host orchestration --------------------------------
static void* symv(const void* s) {
    void* p = nullptr;
    cudaGetSymbolAddress(&p, s);
    return p;
}

template <int EPI, bool NT, bool ACC>
static void launch_gemm16(const __half* A, const __half* B, const float* bias,
                          float* C32, __half* C16, int M, int Nc, int K, float alpha) {
    static bool attr_done = false;
    if (!attr_done) {
        cudaFuncSetAttribute(gemm16_kernel<EPI, NT, ACC>,
                             cudaFuncAttributeMaxDynamicSharedMemorySize, SMEM_BYTES);
        attr_done = true;
    }
    gemm16_kernel<EPI, NT, ACC><<<dim3(Nc / 256, M / 128), 256, SMEM_BYTES>>>(
        A, B, bias, C32, C16, M, Nc, K, alpha);
}

extern "C" void kernel_launch(void* const* d_in, const int* in_sizes, int n_in,
                              void* d_out, int out_size) {
    const float* x      = (const float*)d_in[0];
    const float* fc1_w  = (const float*)d_in[1];
    const float* fc1_b  = (const float*)d_in[2];
    const float* wh_w   = (const float*)d_in[3];
    const float* wh_b   = (const float*)d_in[4];
    const float* wt_w   = (const float*)d_in[5];
    const float* wt_b   = (const float*)d_in[6];
    const float* lin1_w = (const float*)d_in[7];
    const float* lin1_b = (const float*)d_in[8];
    const float* lin2_w = (const float*)d_in[9];
    const float* lin2_b = (const float*)d_in[10];
    const float* att1_w = (const float*)d_in[11];
    const float* att1_b = (const float*)d_in[12];
    const float* att2_w = (const float*)d_in[13];
    const float* att2_b = (const float*)d_in[14];
    const float* ln_g   = (const float*)d_in[15];
    const float* ln_b   = (const float*)d_in[16];
    const float* fc_w   = (const float*)d_in[17];
    const float* fc_b   = (const float*)d_in[18];

    float*  h       = (float*)symv(g_h);
    __half* logits16= (__half*)symv(g_logits16);
    float*  tw      = (float*)symv(g_tw);
    int*    ti      = (int*)symv(g_ti);
    float*  emb     = (float*)symv(g_emb);
    float*  hatt    = (float*)symv(g_hatt);
    float*  att     = (float*)symv(g_att);
    float*  a       = (float*)symv(g_a);
    float*  part    = (float*)symv(g_part);
    float*  cmean   = (float*)symv(g_colmean);
    __half* xh      = (__half*)symv(g_xh);
    __half* h16     = (__half*)symv(g_h16);
    __half* eh16    = (__half*)symv(g_eh16);
    __half* et16    = (__half*)symv(g_et16);
    __half* s1h     = (__half*)symv(g_s1h);
    __half* b1h     = (__half*)symv(g_b1h);
    __half* emb16   = (__half*)symv(g_emb16);
    __half* fc1_wh  = (__half*)symv(g_fc1_wh);
    __half* wh_wh   = (__half*)symv(g_wh_wh);
    __half* wt_wh   = (__half*)symv(g_wt_wh);
    __half* lin1_wh = (__half*)symv(g_lin1_wh);
    __half* lin2_wh = (__half*)symv(g_lin2_wh);
    __half* att1_wh = (__half*)symv(g_att1_wh);

    // 0) fp16 conversions
    conv_half_kernel<<<(NROWS * DIN) / 1024, 256>>>(x, xh);
    conv_half_kernel<<<(DIN * DD) / 1024, 256>>>(fc1_w, fc1_wh);
    conv_half_kernel<<<(DD * DD) / 1024, 256>>>(wh_w, wh_wh);
    conv_half_kernel<<<(DD * DD) / 1024, 256>>>(wt_w, wt_wh);
    conv_half_kernel<<<(DD * DD) / 1024, 256>>>(lin1_w, lin1_wh);
    conv_half_kernel<<<(DD * DD) / 1024, 256>>>(lin2_w, lin2_wh);
    conv_half_kernel<<<(DD * DH) / 1024, 256>>>(att1_w, att1_wh);

    // 1) h = relu(x @ fc1_w + fc1_b)  (fp32 out, for exact colmean)
    launch_gemm16<1, false, false>(xh, fc1_wh, fc1_b, h, nullptr, NROWS, DD, DIN, 1.0f);

    // 2) h16 = half((h + colmean(h)) * 0.5)
    colsum_partial<<<NCHUNK, DD>>>(h, nullptr, part);
    colmean_finish<<<1, DD>>>(part, cmean);
    mean_update<<<(NROWS * DD) / 256, 256>>>(h, cmean, h16);

    // 3) e_h, e_t (fp16 only)
    launch_gemm16<0, false, false>(h16, wh_wh, wh_b, nullptr, eh16, NROWS, DD, DD, 1.0f);
    launch_gemm16<0, false, false>(h16, wt_wh, wt_b, nullptr, et16, NROWS, DD, DD, 1.0f);

    // 4) logits = SCALE * e_h @ e_t^T  (NT, fp16 store)
    launch_gemm16<0, true, false>(eh16, et16, nullptr, nullptr, logits16,
                                  NROWS, NROWS, DD, SCALE_LOGITS);

    // 5) top-6 per row (vectorized fp16 read)
    topk_kernel<<<NROWS / 8, 256>>>(logits16, tw, ti);

    // 6) neighbor aggregation -> s1h, b1h
    aggregate_kernel<<<NROWS, 256>>>(eh16, et16, tw, ti, s1h, b1h);

    // 7) emb = leaky(s1@lin1+b) + leaky(b1@lin2+b)
    launch_gemm16<2, false, false>(s1h, lin1_wh, lin1_b, emb, nullptr, NROWS, DD, DD, 1.0f);
    launch_gemm16<2, false, true >(b1h, lin2_wh, lin2_b, emb, emb16, NROWS, DD, DD, 1.0f);

    // 8) attention readout
    launch_gemm16<2, false, false>(emb16, att1_wh, att1_b, hatt, nullptr, NROWS, DH, DD, 1.0f);
    att_mv_kernel<<<NROWS / 8, 256>>>(hatt, att2_w, att2_b, att);
    softmax_n_kernel<<<1, 1024>>>(att, a);

    // 9) pooled = sum_i a_i * emb_i
    colsum_partial<<<NCHUNK, DD>>>(emb, a, part);

    // 10) LN + fc + softmax + argmax
    final_kernel<<<1, DD>>>(part, ln_g, ln_b, fc_w, fc_b, (float*)d_out, out_size);
}

// round 9
// speedup vs baseline: 1.4015x; 1.0620x over previous
#include <cuda_runtime.h>
#include <cuda_fp16.h>
#include <mma.h>
#include <math.h>
#include <float.h>
#include <stdint.h>
#include <type_traits>

using namespace nvcuda;

#define NROWS 8192
#define DIN   1024
#define DD    512
#define DH    256      // D/2
#define TK    6
#define NCHUNK 64
#define ROWS_PER_CHUNK (NROWS / NCHUNK)
#define LN_EPS 1e-5f
#define SCALE_LOGITS 0.044194173824159216f  // 512^-0.5

// ------------------------- scratch (device globals; no cudaMalloc allowed) ---
__device__ float  g_h[NROWS * DD];
__device__ __half g_logits16[(size_t)NROWS * NROWS];  // 128 MB
__device__ float  g_tw[NROWS * TK];
__device__ int    g_ti[NROWS * TK];
__device__ float  g_emb[NROWS * DD];
__device__ float  g_hatt[NROWS * DH];
__device__ float  g_att[NROWS];
__device__ float  g_a[NROWS];
__device__ float  g_part[NCHUNK * DD];
__device__ float  g_colmean[DD];
// fp16 operand buffers
__device__ __half g_xh[NROWS * DIN];
__device__ __half g_h16[NROWS * DD];
__device__ __half g_eh16[NROWS * DD];
__device__ __half g_et16[NROWS * DD];
__device__ __half g_s1h[NROWS * DD];
__device__ __half g_b1h[NROWS * DD];
__device__ __half g_emb16[NROWS * DD];
// fp16 weights (same [K,N] layout as fp32 originals)
__device__ __half g_fc1_wh[DIN * DD];
__device__ __half g_wh_wh[DD * DD];
__device__ __half g_wt_wh[DD * DD];
__device__ __half g_lin1_wh[DD * DD];
__device__ __half g_lin2_wh[DD * DD];
__device__ __half g_att1_wh[DD * DH];

// ------------------------- cp.async helpers ----------------------------------
__device__ __forceinline__ void cp_async16(void* smem_ptr, const void* gptr) {
    unsigned saddr = (unsigned)__cvta_generic_to_shared(smem_ptr);
    asm volatile("cp.async.cg.shared.global [%0], [%1], 16;\n" :: "r"(saddr), "l"(gptr));
}
__device__ __forceinline__ void cp_commit() { asm volatile("cp.async.commit_group;\n"); }
__device__ __forceinline__ void cp_wait0()  { asm volatile("cp.async.wait_group 0;\n"); }
__device__ __forceinline__ void cp_wait1()  { asm volatile("cp.async.wait_group 1;\n"); }

// ------------------------- fp16 wmma GEMM, occupancy-2 ------------------------
// Block tile 128(M) x 128(N), BK=32, 256 threads = 8 warps (4x2), 32x64/warp.
// NN: B is [K,Nc] half row-major.  NT: B is [Nc,K] half row-major (C = A@B^T).
// EPI: 0=none, 1=relu, 2=leaky(0.01)
#define LDA   40      // halves: 32 + 8 pad
#define LDBN  136     // halves: 128 + 8 pad
#define LDC   68      // floats
#define A_H   (128 * LDA)                    // 5120 halves
#define B_H   5120                            // max(128*LDA=5120, 32*LDBN=4352)
#define STAGE_H (A_H + B_H)                   // 10240 halves = 20480 B
#define NSTAGE 3
#define SMEM_BYTES (NSTAGE * STAGE_H * 2)     // 61440 B -> 2 CTAs/SM

template <bool NT>
__device__ __forceinline__ void load_tiles(__half* As, __half* Bs,
                                           const __half* __restrict__ A,
                                           const __half* __restrict__ B,
                                           int m0, int n0, int k0, int K, int Nc,
                                           int tid) {
    #pragma unroll
    for (int f = tid; f < 512; f += 256) {
        int m = f >> 2, kq = (f & 3) << 3;
        cp_async16(&As[m * LDA + kq], &A[(size_t)(m0 + m) * K + k0 + kq]);
    }
    if (NT) {
        #pragma unroll
        for (int f = tid; f < 512; f += 256) {
            int n = f >> 2, kq = (f & 3) << 3;
            cp_async16(&Bs[n * LDA + kq], &B[(size_t)(n0 + n) * K + k0 + kq]);
        }
    } else {
        #pragma unroll
        for (int f = tid; f < 512; f += 256) {
            int k = f >> 4, nq = (f & 15) << 3;
            cp_async16(&Bs[k * LDBN + nq], &B[(size_t)(k0 + k) * Nc + n0 + nq]);
        }
    }
}

template <int EPI, bool NT, bool ACC>
__global__ __launch_bounds__(256, 2)
void gemm16_kernel(const __half* __restrict__ A, const __half* __restrict__ B,
                   const float* __restrict__ bias, float* __restrict__ C32,
                   __half* __restrict__ C16, int M, int Nc, int K, float alpha) {
    extern __shared__ __half smem[];

    const int tid    = threadIdx.x;
    const int warpId = tid >> 5;
    const int warp_m = warpId >> 1;        // 0..3 -> m offset *32
    const int warp_n = warpId & 1;         // 0..1 -> n offset *64
    const int m_off  = warp_m * 32;
    const int n_off  = warp_n * 64;
    const int m0 = blockIdx.y * 128;
    const int n0 = blockIdx.x * 128;

    using BLayout = typename std::conditional<NT, wmma::col_major, wmma::row_major>::type;

    wmma::fragment<wmma::accumulator, 16, 16, 16, float> acc[2][4];
    #pragma unroll
    for (int i = 0; i < 2; i++)
        #pragma unroll
        for (int j = 0; j < 4; j++)
            wmma::fill_fragment(acc[i][j], 0.0f);

    const int niter = K / 32;

    load_tiles<NT>(smem, smem + A_H, A, B, m0, n0, 0, K, Nc, tid);
    cp_commit();
    if (niter > 1) {
        __half* s1p = smem + STAGE_H;
        load_tiles<NT>(s1p, s1p + A_H, A, B, m0, n0, 32, K, Nc, tid);
    }
    cp_commit();

    int stage = 0;
    for (int it = 0; it < niter; it++) {
        cp_wait1();
        __syncthreads();

        __half* As = smem + stage * STAGE_H;
        __half* Bs = As + A_H;

        int knext = (it + 2) * 32;
        int nstage = stage + 2; if (nstage >= NSTAGE) nstage -= NSTAGE;
        if (knext < K) {
            __half* An = smem + nstage * STAGE_H;
            load_tiles<NT>(An, An + A_H, A, B, m0, n0, knext, K, Nc, tid);
        }
        cp_commit();

        #pragma unroll
        for (int kk = 0; kk < 2; kk++) {
            wmma::fragment<wmma::matrix_a, 16, 16, 16, __half, wmma::row_major> af[2];
            wmma::fragment<wmma::matrix_b, 16, 16, 16, __half, BLayout> bf[4];
            #pragma unroll
            for (int i = 0; i < 2; i++)
                wmma::load_matrix_sync(af[i], &As[(m_off + i * 16) * LDA + kk * 16], LDA);
            #pragma unroll
            for (int j = 0; j < 4; j++) {
                if (NT)
                    wmma::load_matrix_sync(bf[j], &Bs[(n_off + j * 16) * LDA + kk * 16], LDA);
                else
                    wmma::load_matrix_sync(bf[j], &Bs[kk * 16 * LDBN + n_off + j * 16], LDBN);
            }
            #pragma unroll
            for (int i = 0; i < 2; i++)
                #pragma unroll
                for (int j = 0; j < 4; j++)
                    wmma::mma_sync(acc[i][j], af[i], bf[j], acc[i][j]);
        }

        stage++; if (stage >= NSTAGE) stage = 0;
    }

    cp_wait0();

    // Epilogue: two 64-wide n-chunks through shared, alpha/bias/act
    float* Cs = (float*)smem;
    #pragma unroll
    for (int h = 0; h < 2; h++) {
        __syncthreads();
        if (warp_n == h) {
            #pragma unroll
            for (int i = 0; i < 2; i++)
                #pragma unroll
                for (int j = 0; j < 4; j++)
                    wmma::store_matrix_sync(&Cs[(m_off + i * 16) * LDC + j * 16],
                                            acc[i][j], LDC, wmma::mem_row_major);
        }
        __syncthreads();
        for (int e = tid; e < 128 * 64; e += 256) {
            int m = e >> 6, c = e & 63;
            int n = n0 + h * 64 + c;
            float v = Cs[m * LDC + c] * alpha;
            if (bias) v += bias[n];
            if (EPI == 1) v = fmaxf(v, 0.0f);
            else if (EPI == 2) v = (v > 0.0f) ? v : 0.01f * v;
            size_t o = (size_t)(m0 + m) * Nc + n;
            if (ACC) v += C32[o];
            if (C32) C32[o] = v;
            if (C16) C16[o] = __float2half(v);
        }
    }
}

// ------------------------- conversion kernel ----------------------------------
__global__ void conv_half_kernel(const float* __restrict__ X, __half* __restrict__ Xh) {
    int i = (blockIdx.x * blockDim.x + threadIdx.x) * 4;
    float4 v = *reinterpret_cast<const float4*>(&X[i]);
    *reinterpret_cast<__half2*>(&Xh[i])     = __floats2half2_rn(v.x, v.y);
    *reinterpret_cast<__half2*>(&Xh[i + 2]) = __floats2half2_rn(v.z, v.w);
}

// ------------------------- column sum (optionally row-weighted) --------------
__global__ void colsum_partial(const float* __restrict__ X,
                               const float* __restrict__ w,
                               float* __restrict__ part) {
    int d = threadIdx.x;
    int r0 = blockIdx.x * ROWS_PER_CHUNK;
    float s = 0.0f;
    for (int r = 0; r < ROWS_PER_CHUNK; r++) {
        float v = X[(size_t)(r0 + r) * DD + d];
        if (w) v *= w[r0 + r];
        s += v;
    }
    part[blockIdx.x * DD + d] = s;
}

__global__ void colmean_finish(const float* __restrict__ part, float* __restrict__ mean) {
    int d = threadIdx.x;
    float s = 0.0f;
    for (int c = 0; c < NCHUNK; c++) s += part[c * DD + d];
    mean[d] = s / (float)NROWS;
}

__global__ void mean_update(const float* __restrict__ h32, const float* __restrict__ mean,
                            __half* __restrict__ h16) {
    int i = blockIdx.x * blockDim.x + threadIdx.x;
    h16[i] = __float2half((h32[i] + mean[i & (DD - 1)]) * 0.5f);
}

// ------------------------- top-6 per row (warp/row, vectorized fp16) ---------
__global__ void topk_kernel(const __half* __restrict__ logits,
                            float* __restrict__ tw, int* __restrict__ ti) {
    const unsigned FULL = 0xFFFFFFFFu;
    int warp = threadIdx.x >> 5;
    int lane = threadIdx.x & 31;
    int row = blockIdx.x * 8 + warp;

    const __half* rp = logits + (size_t)row * NROWS;

    float val[TK];
    int   idx[TK];
    #pragma unroll
    for (int k = 0; k < TK; k++) { val[k] = -FLT_MAX; idx[k] = 0x7FFFFFFF; }

    for (int it = 0; it < NROWS / 256; it++) {
        int jbase = it * 256 + lane * 8;
        uint4 pkt = *reinterpret_cast<const uint4*>(rp + jbase);
        const __half* hp = reinterpret_cast<const __half*>(&pkt);
        #pragma unroll
        for (int e = 0; e < 8; e++) {
            float v = __half2float(hp[e]);
            if (v > val[TK - 1]) {
                int j = jbase + e;
                int pos = TK - 1;
                #pragma unroll
                for (int k = TK - 2; k >= 0; k--) {
                    if (v > val[k]) { val[k + 1] = val[k]; idx[k + 1] = idx[k]; pos = k; }
                }
                val[pos] = v; idx[pos] = j;
            }
        }
    }

    int head = 0;
    for (int r = 0; r < TK; r++) {
        float bv = (head < TK) ? val[head] : -FLT_MAX;
        int   bi = (head < TK) ? idx[head] : 0x7FFFFFFF;
        int   bl = lane;
        #pragma unroll
        for (int off = 16; off > 0; off >>= 1) {
            float ov = __shfl_down_sync(FULL, bv, off);
            int   oi = __shfl_down_sync(FULL, bi, off);
            int   ol = __shfl_down_sync(FULL, bl, off);
            if (ov > bv || (ov == bv && oi < bi)) { bv = ov; bi = oi; bl = ol; }
        }
        bv = __shfl_sync(FULL, bv, 0);
        bi = __shfl_sync(FULL, bi, 0);
        bl = __shfl_sync(FULL, bl, 0);
        if (lane == 0) { tw[row * TK + r] = bv; ti[row * TK + r] = bi; }
        if (lane == bl) head++;
    }
}

// ------------------------- per-row neighbor aggregation (fp16 inputs) --------
__global__ __launch_bounds__(256)
void aggregate_kernel(const __half* __restrict__ eh16, const __half* __restrict__ et16,
                      const float* __restrict__ tw, const int* __restrict__ ti,
                      __half* __restrict__ s1h, __half* __restrict__ b1h) {
    __shared__ float red[256];
    __shared__ float sh_ka[TK];
    int row = blockIdx.x;
    int t = threadIdx.x;

    float p[TK];
    {
        float mx = -FLT_MAX;
        #pragma unroll
        for (int k = 0; k < TK; k++) { p[k] = tw[row * TK + k]; mx = fmaxf(mx, p[k]); }
        float s = 0.0f;
        #pragma unroll
        for (int k = 0; k < TK; k++) { p[k] = expf(p[k] - mx); s += p[k]; }
        #pragma unroll
        for (int k = 0; k < TK; k++) p[k] /= s;
    }

    float eh0 = __half2float(eh16[(size_t)row * DD + t]);
    float eh1 = __half2float(eh16[(size_t)row * DD + t + 256]);
    float Nb[TK][2];

    for (int k = 0; k < TK; k++) {
        int j = ti[row * TK + k];
        Nb[k][0] = __half2float(et16[(size_t)j * DD + t]);
        Nb[k][1] = __half2float(et16[(size_t)j * DD + t + 256]);
        float g0 = tanhf(fmaf(2.0f - p[k], eh0, p[k] * Nb[k][0]));
        float g1 = tanhf(fmaf(2.0f - p[k], eh1, p[k] * Nb[k][1]));
        float partial = Nb[k][0] * g0 + Nb[k][1] * g1;
        red[t] = partial; __syncthreads();
        for (int s = 128; s > 0; s >>= 1) {
            if (t < s) red[t] += red[t + s];
            __syncthreads();
        }
        if (t == 0) sh_ka[k] = red[0];
        __syncthreads();
    }

    float kp[TK];
    {
        float mx = -FLT_MAX;
        #pragma unroll
        for (int k = 0; k < TK; k++) { kp[k] = sh_ka[k]; mx = fmaxf(mx, kp[k]); }
        float s = 0.0f;
        #pragma unroll
        for (int k = 0; k < TK; k++) { kp[k] = expf(kp[k] - mx); s += kp[k]; }
        #pragma unroll
        for (int k = 0; k < TK; k++) kp[k] /= s;
    }

    float en0 = 0.0f, en1 = 0.0f;
    #pragma unroll
    for (int k = 0; k < TK; k++) { en0 = fmaf(kp[k], Nb[k][0], en0); en1 = fmaf(kp[k], Nb[k][1], en1); }

    s1h[(size_t)row * DD + t]       = __float2half(eh0 + en0);
    s1h[(size_t)row * DD + t + 256] = __float2half(eh1 + en1);
    b1h[(size_t)row * DD + t]       = __float2half(eh0 * en0);
    b1h[(size_t)row * DD + t + 256] = __float2half(eh1 * en1);
}

// ------------------------- attention readout ---------------------------------
__global__ void att_mv_kernel(const float* __restrict__ hatt,
                              const float* __restrict__ w2, const float* __restrict__ b2,
                              float* __restrict__ att) {
    const unsigned FULL = 0xFFFFFFFFu;
    int warp = threadIdx.x >> 5;
    int lane = threadIdx.x & 31;
    int row = blockIdx.x * 8 + warp;
    float s = 0.0f;
    for (int d = lane; d < DH; d += 32)
        s = fmaf(hatt[(size_t)row * DH + d], w2[d], s);
    #pragma unroll
    for (int off = 16; off > 0; off >>= 1) s += __shfl_down_sync(FULL, s, off);
    if (lane == 0) att[row] = s + b2[0];
}

__global__ void softmax_n_kernel(const float* __restrict__ att, float* __restrict__ a) {
    __shared__ float red[1024];
    __shared__ float s_max, s_sum;
    int t = threadIdx.x;
    float lm = -FLT_MAX;
    for (int i = t; i < NROWS; i += 1024) lm = fmaxf(lm, att[i]);
    red[t] = lm; __syncthreads();
    for (int s = 512; s > 0; s >>= 1) { if (t < s) red[t] = fmaxf(red[t], red[t + s]); __syncthreads(); }
    if (t == 0) s_max = red[0];
    __syncthreads();
    float ls = 0.0f;
    for (int i = t; i < NROWS; i += 1024) ls += expf(att[i] - s_max);
    red[t] = ls; __syncthreads();
    for (int s = 512; s > 0; s >>= 1) { if (t < s) red[t] += red[t + s]; __syncthreads(); }
    if (t == 0) s_sum = red[0];
    __syncthreads();
    float inv = 1.0f / s_sum;
    for (int i = t; i < NROWS; i += 1024) a[i] = expf(att[i] - s_max) * inv;
}

// ------------------------- final: LN + fc + softmax + argmax -----------------
__global__ void final_kernel(const float* __restrict__ part,
                             const float* __restrict__ ln_g, const float* __restrict__ ln_b,
                             const float* __restrict__ fc_w, const float* __restrict__ fc_b,
                             float* __restrict__ out, int out_size) {
    __shared__ float red[DD];
    int d = threadIdx.x;
    float pooled = 0.0f;
    for (int c = 0; c < NCHUNK; c++) pooled += part[c * DD + d];

    red[d] = pooled; __syncthreads();
    for (int s = 256; s > 0; s >>= 1) { if (d < s) red[d] += red[d + s]; __syncthreads(); }
    float mu = red[0] / (float)DD;
    __syncthreads();

    float cen = pooled - mu;
    red[d] = cen * cen; __syncthreads();
    for (int s = 256; s > 0; s >>= 1) { if (d < s) red[d] += red[d + s]; __syncthreads(); }
    float var = red[0] / (float)DD;
    __syncthreads();

    float ln = cen * rsqrtf(var + LN_EPS) * ln_g[d] + ln_b[d];

    red[d] = ln * fc_w[2 * d + 0]; __syncthreads();
    for (int s = 256; s > 0; s >>= 1) { if (d < s) red[d] += red[d + s]; __syncthreads(); }
    float o0 = red[0] + fc_b[0];
    __syncthreads();

    red[d] = ln * fc_w[2 * d + 1]; __syncthreads();
    for (int s = 256; s > 0; s >>= 1) { if (d < s) red[d] += red[d + s]; __syncthreads(); }
    float o1 = red[0] + fc_b[1];

    if (d == 0) {
        float m = fmaxf(o0, o1);
        float e0 = expf(o0 - m), e1 = expf(o1 - m);
        float inv = 1.0f / (e0 + e1);
        if (out_size > 0) out[0] = o0;
        if (out_size > 1) out[1] = o1;
        if (out_size > 2) out[2] = e0 * inv;
        if (out_size > 3) out[3] = e1 * inv;
        if (out_size > 4) out[4] = (o1 > o0) ? 1.0f : 0.0f;
    }
}

// ------------------------- host orchestration --------------------------------
static void* symv(const void* s) {
    void* p = nullptr;
    cudaGetSymbolAddress(&p, s);
    return p;
}

template <int EPI, bool NT, bool ACC>
static void launch_gemm16(const __half* A, const __half* B, const float* bias,
                          float* C32, __half* C16, int M, int Nc, int K, float alpha) {
    static bool attr_done = false;
    if (!attr_done) {
        cudaFuncSetAttribute(gemm16_kernel<EPI, NT, ACC>,
                             cudaFuncAttributeMaxDynamicSharedMemorySize, SMEM_BYTES);
        attr_done = true;
    }
    gemm16_kernel<EPI, NT, ACC><<<dim3(Nc / 128, M / 128), 256, SMEM_BYTES>>>(
        A, B, bias, C32, C16, M, Nc, K, alpha);
}

extern "C" void kernel_launch(void* const* d_in, const int* in_sizes, int n_in,
                              void* d_out, int out_size) {
    const float* x      = (const float*)d_in[0];
    const float* fc1_w  = (const float*)d_in[1];
    const float* fc1_b  = (const float*)d_in[2];
    const float* wh_w   = (const float*)d_in[3];
    const float* wh_b   = (const float*)d_in[4];
    const float* wt_w   = (const float*)d_in[5];
    const float* wt_b   = (const float*)d_in[6];
    const float* lin1_w = (const float*)d_in[7];
    const float* lin1_b = (const float*)d_in[8];
    const float* lin2_w = (const float*)d_in[9];
    const float* lin2_b = (const float*)d_in[10];
    const float* att1_w = (const float*)d_in[11];
    const float* att1_b = (const float*)d_in[12];
    const float* att2_w = (const float*)d_in[13];
    const float* att2_b = (const float*)d_in[14];
    const float* ln_g   = (const float*)d_in[15];
    const float* ln_b   = (const float*)d_in[16];
    const float* fc_w   = (const float*)d_in[17];
    const float* fc_b   = (const float*)d_in[18];

    float*  h       = (float*)symv(g_h);
    __half* logits16= (__half*)symv(g_logits16);
    float*  tw      = (float*)symv(g_tw);
    int*    ti      = (int*)symv(g_ti);
    float*  emb     = (float*)symv(g_emb);
    float*  hatt    = (float*)symv(g_hatt);
    float*  att     = (float*)symv(g_att);
    float*  a       = (float*)symv(g_a);
    float*  part    = (float*)symv(g_part);
    float*  cmean   = (float*)symv(g_colmean);
    __half* xh      = (__half*)symv(g_xh);
    __half* h16     = (__half*)symv(g_h16);
    __half* eh16    = (__half*)symv(g_eh16);
    __half* et16    = (__half*)symv(g_et16);
    __half* s1h     = (__half*)symv(g_s1h);
    __half* b1h     = (__half*)symv(g_b1h);
    __half* emb16   = (__half*)symv(g_emb16);
    __half* fc1_wh  = (__half*)symv(g_fc1_wh);
    __half* wh_wh   = (__half*)symv(g_wh_wh);
    __half* wt_wh   = (__half*)symv(g_wt_wh);
    __half* lin1_wh = (__half*)symv(g_lin1_wh);
    __half* lin2_wh = (__half*)symv(g_lin2_wh);
    __half* att1_wh = (__half*)symv(g_att1_wh);

    // 0) fp16 conversions
    conv_half_kernel<<<(NROWS * DIN) / 1024, 256>>>(x, xh);
    conv_half_kernel<<<(DIN * DD) / 1024, 256>>>(fc1_w, fc1_wh);
    conv_half_kernel<<<(DD * DD) / 1024, 256>>>(wh_w, wh_wh);
    conv_half_kernel<<<(DD * DD) / 1024, 256>>>(wt_w, wt_wh);
    conv_half_kernel<<<(DD * DD) / 1024, 256>>>(lin1_w, lin1_wh);
    conv_half_kernel<<<(DD * DD) / 1024, 256>>>(lin2_w, lin2_wh);
    conv_half_kernel<<<(DD * DH) / 1024, 256>>>(att1_w, att1_wh);

    // 1) h = relu(x @ fc1_w + fc1_b)  (fp32 out, for exact colmean)
    launch_gemm16<1, false, false>(xh, fc1_wh, fc1_b, h, nullptr, NROWS, DD, DIN, 1.0f);

    // 2) h16 = half((h + colmean(h)) * 0.5)
    colsum_partial<<<NCHUNK, DD>>>(h, nullptr, part);
    colmean_finish<<<1, DD>>>(part, cmean);
    mean_update<<<(NROWS * DD) / 256, 256>>>(h, cmean, h16);

    // 3) e_h, e_t (fp16 only)
    launch_gemm16<0, false, false>(h16, wh_wh, wh_b, nullptr, eh16, NROWS, DD, DD, 1.0f);
    launch_gemm16<0, false, false>(h16, wt_wh, wt_b, nullptr, et16, NROWS, DD, DD, 1.0f);

    // 4) logits = SCALE * e_h @ e_t^T  (NT, fp16 store)
    launch_gemm16<0, true, false>(eh16, et16, nullptr, nullptr, logits16,
                                  NROWS, NROWS, DD, SCALE_LOGITS);

    // 5) top-6 per row (vectorized fp16 read)
    topk_kernel<<<NROWS / 8, 256>>>(logits16, tw, ti);

    // 6) neighbor aggregation -> s1h, b1h
    aggregate_kernel<<<NROWS, 256>>>(eh16, et16, tw, ti, s1h, b1h);

    // 7) emb = leaky(s1@lin1+b) + leaky(b1@lin2+b)
    launch_gemm16<2, false, false>(s1h, lin1_wh, lin1_b, emb, nullptr, NROWS, DD, DD, 1.0f);
    launch_gemm16<2, false, true >(b1h, lin2_wh, lin2_b, emb, emb16, NROWS, DD, DD, 1.0f);

    // 8) attention readout
    launch_gemm16<2, false, false>(emb16, att1_wh, att1_b, hatt, nullptr, NROWS, DH, DD, 1.0f);
    att_mv_kernel<<<NROWS / 8, 256>>>(hatt, att2_w, att2_b, att);
    softmax_n_kernel<<<1, 1024>>>(att, a);

    // 9) pooled = sum_i a_i * emb_i
    colsum_partial<<<NCHUNK, DD>>>(emb, a, part);

    // 10) LN + fc + softmax + argmax
    final_kernel<<<1, DD>>>(part, ln_g, ln_b, fc_w, fc_b, (float*)d_out, out_size);
}